// round 3
// baseline (speedup 1.0000x reference)
#include <cuda_runtime.h>
#include <math.h>

#define D_ 256
#define H_ 256
#define B_ 128
#define E_ 128
#define STEPS_ 5
#define NMAX 100352

// ---------------- scratch (static __device__, no allocations) ----------------
__device__ __align__(16) float g_tmp[NMAX * H_];      // FNN layer1 output (ELU'd)
__device__ __align__(16) float g_hfeat[NMAX * H_];    // FNN output
__device__ float g_e[NMAX];                           // attention logits
__device__ __align__(16) float g_gpart[2 * B_ * 4 * H_]; // split-K gate partials
__device__ float g_hbuf[2][3][B_ * H_];               // LSTM h ping-pong
__device__ float g_c[3][B_ * H_];                     // LSTM c
__device__ float g_qstar[B_ * 2 * H_];                // [q | r]
__device__ int   g_seg[B_ + 1];                       // segment offsets

// ---------------- init: zero mutable state every call ----------------
__global__ void k_init() {
    int i = blockIdx.x * blockDim.x + threadIdx.x;
    int stride = gridDim.x * blockDim.x;
    for (int j = i; j < B_ * 2 * H_; j += stride) g_qstar[j] = 0.f;
    for (int j = i; j < 3 * B_ * H_; j += stride) {
        g_hbuf[0][0][j] = 0.f;
        g_hbuf[1][0][j] = 0.f;
        g_c[0][j] = 0.f;
    }
}

// ---------------- segment offsets via binary search (batch_idxs sorted) ------
__global__ void k_seg(const int* __restrict__ idx, int N) {
    int b = threadIdx.x;          // 0..B_
    if (b > B_) return;
    int lo = 0, hi = N;
    while (lo < hi) {
        int mid = (lo + hi) >> 1;
        if (idx[mid] < b) lo = mid + 1; else hi = mid;
    }
    g_seg[b] = lo;
}

// ---------------- FNN GEMM: C = act(A[nrows,256] @ W[256,256] + bias) --------
// 64-row x 256-col block tile, 256 threads, 8x8 micro-tile per thread.
template <bool ELU>
__global__ __launch_bounds__(256, 2) void k_fnn(
    const float* __restrict__ A, const float* __restrict__ W,
    const float* __restrict__ bias, float* __restrict__ C, int nrows)
{
    __shared__ float a_s[64][17];
    __shared__ float w_s[16][256];
    const int tid  = threadIdx.x;
    const int row0 = blockIdx.x * 64;
    const int wy   = tid >> 5;      // 0..7 (warp id)
    const int lane = tid & 31;
    const int lrow = tid >> 2;      // 0..63
    const int lcol = (tid & 3) * 4; // 0,4,8,12

    float acc[8][8];
#pragma unroll
    for (int r = 0; r < 8; r++)
#pragma unroll
        for (int c = 0; c < 8; c++) acc[r][c] = 0.f;

    for (int kt = 0; kt < 256; kt += 16) {
        // load A tile 64x16
        {
            int gr = row0 + lrow;
            float4 av = make_float4(0.f, 0.f, 0.f, 0.f);
            if (gr < nrows) av = *(const float4*)(A + (size_t)gr * 256 + kt + lcol);
            a_s[lrow][lcol + 0] = av.x; a_s[lrow][lcol + 1] = av.y;
            a_s[lrow][lcol + 2] = av.z; a_s[lrow][lcol + 3] = av.w;
        }
        // load W tile 16x256
#pragma unroll
        for (int i = 0; i < 4; i++) {
            int idx4 = tid + 256 * i;
            int r = idx4 >> 6, c4 = (idx4 & 63) * 4;
            *(float4*)&w_s[r][c4] = *(const float4*)(W + (size_t)(kt + r) * 256 + c4);
        }
        __syncthreads();
#pragma unroll
        for (int kk = 0; kk < 16; kk++) {
            float a[8], bb[8];
#pragma unroll
            for (int r = 0; r < 8; r++) a[r] = a_s[wy + 8 * r][kk];
#pragma unroll
            for (int c = 0; c < 8; c++) bb[c] = w_s[kk][lane + 32 * c];
#pragma unroll
            for (int r = 0; r < 8; r++)
#pragma unroll
                for (int c = 0; c < 8; c++) acc[r][c] += a[r] * bb[c];
        }
        __syncthreads();
    }
#pragma unroll
    for (int r = 0; r < 8; r++) {
        int gr = row0 + wy + 8 * r;
        if (gr < nrows) {
#pragma unroll
            for (int c = 0; c < 8; c++) {
                int col = lane + 32 * c;
                float v = acc[r][c] + bias[col];
                if (ELU) v = (v > 0.f) ? v : expm1f(v);
                C[(size_t)gr * 256 + col] = v;
            }
        }
    }
}

// ---------------- LSTM gates GEMM: gates = xin@Wih^T + h@Whh^T ---------------
// 32x32 tile, split-K=2 via blockIdx.z, partials to g_gpart.
__global__ __launch_bounds__(256) void k_gates(
    const float* __restrict__ xin, int KW,
    const float* __restrict__ hold,
    const float* __restrict__ Wih, const float* __restrict__ Whh,
    float* __restrict__ gpart)
{
    __shared__ float a_s[32][33];
    __shared__ float w_s[32][33];
    const int tid = threadIdx.x;
    const int b0 = blockIdx.x * 32, j0 = blockIdx.y * 32;
    const int KT = KW + H_;
    const int khalf = KT >> 1;
    const int kbeg = blockIdx.z * khalf, kend = kbeg + khalf;
    const int ty = tid >> 4, tx = tid & 15;
    const int lr = tid >> 3, lc = (tid & 7) * 4;
    float a00 = 0.f, a01 = 0.f, a10 = 0.f, a11 = 0.f;

    for (int kt = kbeg; kt < kend; kt += 32) {
        const float *As, *Ws; int k, str;
        if (kt < KW) { As = xin;  Ws = Wih; k = kt;      str = KW; }
        else         { As = hold; Ws = Whh; k = kt - KW; str = H_; }
        float4 av = *(const float4*)(As + (size_t)(b0 + lr) * str + k + lc);
        a_s[lr][lc + 0] = av.x; a_s[lr][lc + 1] = av.y;
        a_s[lr][lc + 2] = av.z; a_s[lr][lc + 3] = av.w;
        float4 wv = *(const float4*)(Ws + (size_t)(j0 + lr) * str + k + lc);
        w_s[lr][lc + 0] = wv.x; w_s[lr][lc + 1] = wv.y;
        w_s[lr][lc + 2] = wv.z; w_s[lr][lc + 3] = wv.w;
        __syncthreads();
#pragma unroll
        for (int kk = 0; kk < 32; kk++) {
            float x0 = a_s[ty][kk], x1 = a_s[ty + 16][kk];
            float w0 = w_s[tx][kk], w1 = w_s[tx + 16][kk];
            a00 += x0 * w0; a01 += x0 * w1;
            a10 += x1 * w0; a11 += x1 * w1;
        }
        __syncthreads();
    }
    float* gp = gpart + (size_t)blockIdx.z * (B_ * 4 * H_);
    gp[(size_t)(b0 + ty)      * 1024 + j0 + tx]      = a00;
    gp[(size_t)(b0 + ty)      * 1024 + j0 + tx + 16] = a01;
    gp[(size_t)(b0 + ty + 16) * 1024 + j0 + tx]      = a10;
    gp[(size_t)(b0 + ty + 16) * 1024 + j0 + tx + 16] = a11;
}

// ---------------- LSTM cell elementwise ----------------
__device__ __forceinline__ float sigf(float x) { return 1.f / (1.f + expf(-x)); }

__global__ void k_update(const float* __restrict__ gp0, const float* __restrict__ gp1,
                         const float* __restrict__ bih, const float* __restrict__ bhh,
                         float* __restrict__ c, float* __restrict__ hnew,
                         float* __restrict__ qdst)
{
    int b = blockIdx.x, j = threadIdx.x;   // 128 blocks x 256 threads
    size_t g0 = (size_t)b * 1024;
    float iv = gp0[g0 + j]       + gp1[g0 + j]       + bih[j]       + bhh[j];
    float fv = gp0[g0 + 256 + j] + gp1[g0 + 256 + j] + bih[256 + j] + bhh[256 + j];
    float gv = gp0[g0 + 512 + j] + gp1[g0 + 512 + j] + bih[512 + j] + bhh[512 + j];
    float ov = gp0[g0 + 768 + j] + gp1[g0 + 768 + j] + bih[768 + j] + bhh[768 + j];
    float cn = sigf(fv) * c[b * H_ + j] + sigf(iv) * tanhf(gv);
    c[b * H_ + j] = cn;
    float hn = sigf(ov) * tanhf(cn);
    hnew[b * H_ + j] = hn;
    if (qdst) qdst[b * 2 * H_ + j] = hn;   // q-part of q_star
}

// ---------------- segment attention: one block per segment ------------------
__global__ __launch_bounds__(256) void k_attn(
    const float* __restrict__ hfeat, const float* __restrict__ q,
    float* __restrict__ qstar)
{
    const int b = blockIdx.x, tid = threadIdx.x;
    const int s0 = g_seg[b], s1 = g_seg[b + 1];
    __shared__ float q_s[256];
    __shared__ float ws[256];
    __shared__ float red[10];
    q_s[tid] = q[b * 256 + tid];
    __syncthreads();

    const int lane = tid & 31, w = tid >> 5;
    float qreg[8];
#pragma unroll
    for (int k = 0; k < 8; k++) qreg[k] = q_s[lane + 32 * k];

    // pass 1: logits + max (warp per node)
    float mloc = -INFINITY;
    for (int n = s0 + w; n < s1; n += 8) {
        const float* hr = hfeat + (size_t)n * 256;
        float p = 0.f;
#pragma unroll
        for (int k = 0; k < 8; k++) p += hr[lane + 32 * k] * qreg[k];
#pragma unroll
        for (int off = 16; off; off >>= 1) p += __shfl_xor_sync(0xffffffffu, p, off);
        if (lane == 0) g_e[n] = p;
        mloc = fmaxf(mloc, p);
    }
    if (lane == 0) red[w] = mloc;
    __syncthreads();
    if (tid == 0) {
        float mm = -INFINITY;
        for (int i = 0; i < 8; i++) mm = fmaxf(mm, red[i]);
        red[8] = isfinite(mm) ? mm : 0.f;
    }
    __syncthreads();
    const float m = red[8];

    // pass 2: chunked exp weights + weighted row accumulation (col per thread)
    float acc0 = 0.f, acc1 = 0.f, acc2 = 0.f, acc3 = 0.f, dpart = 0.f;
    for (int c0 = s0; c0 < s1; c0 += 256) {
        int cnt = min(256, s1 - c0);
        if (tid < cnt) {
            float wv = expf(g_e[c0 + tid] - m);
            ws[tid] = wv;
            dpart += wv;
        }
        __syncthreads();
        const float* base = hfeat + (size_t)c0 * 256 + tid;
        int i = 0;
        for (; i + 4 <= cnt; i += 4) {
            acc0 += ws[i]     * base[(size_t)i * 256];
            acc1 += ws[i + 1] * base[(size_t)(i + 1) * 256];
            acc2 += ws[i + 2] * base[(size_t)(i + 2) * 256];
            acc3 += ws[i + 3] * base[(size_t)(i + 3) * 256];
        }
        for (; i < cnt; i++) acc0 += ws[i] * base[(size_t)i * 256];
        __syncthreads();
    }
    // reduce denom
#pragma unroll
    for (int off = 16; off; off >>= 1) dpart += __shfl_xor_sync(0xffffffffu, dpart, off);
    if (lane == 0) red[w] = dpart;
    __syncthreads();
    if (tid == 0) {
        float s = 0.f;
        for (int i = 0; i < 8; i++) s += red[i];
        red[9] = s + 1e-16f;
    }
    __syncthreads();
    float denom = red[9];
    qstar[b * 2 * H_ + 256 + tid] = (acc0 + acc1 + acc2 + acc3) / denom;
}

// ---------------- output projection: out = q_star @ out_W + out_b -----------
__global__ void k_out(const float* __restrict__ qstar, const float* __restrict__ W,
                      const float* __restrict__ bias, float* __restrict__ out)
{
    int b = blockIdx.x, e = threadIdx.x;   // 128 x 128
    __shared__ float qs[512];
    qs[e] = qstar[b * 512 + e];
    qs[e + 128] = qstar[b * 512 + e + 128];
    qs[e + 256] = qstar[b * 512 + e + 256];
    qs[e + 384] = qstar[b * 512 + e + 384];
    __syncthreads();
    float acc = bias[e];
#pragma unroll 8
    for (int k = 0; k < 512; k++) acc += qs[k] * W[k * E_ + e];
    out[b * E_ + e] = acc;
}

// ---------------- launch ----------------
extern "C" void kernel_launch(void* const* d_in, const int* in_sizes, int n_in,
                              void* d_out, int out_size)
{
    const float* x    = (const float*)d_in[0];
    const int*   bidx = (const int*)d_in[1];
    const float* W1   = (const float*)d_in[2];
    const float* b1   = (const float*)d_in[3];
    const float* W2   = (const float*)d_in[4];
    const float* b2   = (const float*)d_in[5];
    const float* Wih[3] = {(const float*)d_in[6],  (const float*)d_in[10], (const float*)d_in[14]};
    const float* Whh[3] = {(const float*)d_in[7],  (const float*)d_in[11], (const float*)d_in[15]};
    const float* bih[3] = {(const float*)d_in[8],  (const float*)d_in[12], (const float*)d_in[16]};
    const float* bhh[3] = {(const float*)d_in[9],  (const float*)d_in[13], (const float*)d_in[17]};
    const float* outW = (const float*)d_in[18];
    const float* outb = (const float*)d_in[19];
    float* out = (float*)d_out;

    const int N = in_sizes[0] / D_;

    float *tmp_p, *hfeat_p, *gpart_p, *hbuf_p, *c_p, *qstar_p;
    cudaGetSymbolAddress((void**)&tmp_p,   g_tmp);
    cudaGetSymbolAddress((void**)&hfeat_p, g_hfeat);
    cudaGetSymbolAddress((void**)&gpart_p, g_gpart);
    cudaGetSymbolAddress((void**)&hbuf_p,  g_hbuf);
    cudaGetSymbolAddress((void**)&c_p,     g_c);
    cudaGetSymbolAddress((void**)&qstar_p, g_qstar);

    k_init<<<256, 256>>>();
    k_seg<<<1, B_ + 1>>>(bidx, N);

    int nblk = (N + 63) / 64;
    k_fnn<true ><<<nblk, 256>>>(x,     W1, b1, tmp_p,   N);
    k_fnn<false><<<nblk, 256>>>(tmp_p, W2, b2, hfeat_p, N);

    for (int s = 0; s < STEPS_; s++) {
        float* hold = hbuf_p + (size_t)(s & 1) * 3 * B_ * H_;
        float* hnew = hbuf_p + (size_t)((s & 1) ^ 1) * 3 * B_ * H_;
        for (int l = 0; l < 3; l++) {
            const float* xin = (l == 0) ? (const float*)qstar_p
                                        : (const float*)(hnew + (size_t)(l - 1) * B_ * H_);
            int KW = (l == 0) ? 2 * H_ : H_;
            dim3 gg(B_ / 32, 4 * H_ / 32, 2);
            k_gates<<<gg, 256>>>(xin, KW, hold + (size_t)l * B_ * H_,
                                 Wih[l], Whh[l], gpart_p);
            k_update<<<B_, H_>>>(gpart_p, gpart_p + (size_t)B_ * 4 * H_,
                                 bih[l], bhh[l],
                                 c_p + (size_t)l * B_ * H_,
                                 hnew + (size_t)l * B_ * H_,
                                 (l == 2) ? qstar_p : nullptr);
        }
        k_attn<<<B_, 256>>>(hfeat_p, hnew + (size_t)2 * B_ * H_, qstar_p);
    }
    k_out<<<B_, E_>>>(qstar_p, outW, outb, out);
}

// round 5
// speedup vs baseline: 1.3945x; 1.3945x over previous
#include <cuda_runtime.h>
#include <math.h>
#include <stdint.h>

#define D_ 256
#define H_ 256
#define B_ 128
#define E_ 128
#define STEPS_ 5
#define NMAX 100352

// ---------------- scratch (static __device__, no allocations) ----------------
__device__ __align__(16) float g_tmp[NMAX * H_];      // FNN layer1 output (ELU'd)
__device__ __align__(16) float g_hfeat[NMAX * H_];    // FNN output
__device__ float g_e[NMAX];                           // attention logits
__device__ __align__(16) float g_gpart[2 * B_ * 4 * H_]; // split-K gate partials
__device__ float g_hbuf[2][3][B_ * H_];               // LSTM h ping-pong
__device__ float g_c[3][B_ * H_];                     // LSTM c
__device__ float g_qstar[B_ * 2 * H_];                // [q | r]
__device__ int   g_seg[B_ + 1];                       // segment offsets
__device__ __align__(16) float g_Wt1[D_ * H_];        // W1 transposed [N,K]
__device__ __align__(16) float g_Wt2[H_ * H_];        // W2 transposed [N,K]

__device__ __forceinline__ uint32_t cvt_tf32(float f) {
    uint32_t r;
    asm("cvt.rn.tf32.f32 %0, %1;" : "=r"(r) : "f"(f));
    return r;
}

// ---------------- init ----------------
__global__ void k_init() {
    int i = blockIdx.x * blockDim.x + threadIdx.x;
    int stride = gridDim.x * blockDim.x;
    for (int j = i; j < B_ * 2 * H_; j += stride) g_qstar[j] = 0.f;
    for (int j = i; j < 3 * B_ * H_; j += stride) {
        g_hbuf[0][0][j] = 0.f;
        g_hbuf[1][0][j] = 0.f;
        g_c[0][j] = 0.f;
    }
}

// ---------------- weight transpose: Wt[i][j] = W[j][i] (256x256) -------------
__global__ void k_transpose(const float* __restrict__ W, float* __restrict__ Wt) {
    __shared__ float t[32][33];
    int bx = blockIdx.x * 32, by = blockIdx.y * 32;
    int tx = threadIdx.x, ty = threadIdx.y;
    t[ty][tx] = W[(by + ty) * 256 + bx + tx];
    __syncthreads();
    Wt[(bx + ty) * 256 + by + tx] = t[tx][ty];
}

// ---------------- segment offsets ----------------
__global__ void k_seg(const int* __restrict__ idx, int N) {
    int b = threadIdx.x;
    if (b > B_) return;
    int lo = 0, hi = N;
    while (lo < hi) {
        int mid = (lo + hi) >> 1;
        if (idx[mid] < b) lo = mid + 1; else hi = mid;
    }
    g_seg[b] = lo;
}

// ---------------- FNN GEMM via mma.sync tf32 (HMMA) --------------------------
// C[row0:row0+128, col0:col0+128] = act(A[.,256] @ Wt^T + bias)
// Block: 256 threads = 8 warps (2 M x 4 N). Warp tile 64x32 (4x4 m16n8k8).
// Smem tiles stride 68 floats: 68 % 32 == 4 -> conflict-free fragment loads.
#define KC 64
#define LDT 68
#define SM_TILE (128 * LDT)          // floats per tile
#define SM_BYTES (2 * SM_TILE * 4)   // 69632 bytes

template <bool ELU>
__global__ __launch_bounds__(256) void k_fnn_mma(
    const float* __restrict__ A, const float* __restrict__ Wt,
    const float* __restrict__ bias, float* __restrict__ C, int nrows)
{
    extern __shared__ float smem[];
    float* As = smem;             // [128][LDT] rows=m, cols=k
    float* Bs = smem + SM_TILE;   // [128][LDT] rows=n, cols=k
    __shared__ float bias_s[128];

    const int tid  = threadIdx.x;
    const int lane = tid & 31;
    const int warp = tid >> 5;
    const int wm = warp >> 2;        // 0..1
    const int wn = warp & 3;         // 0..3
    const int row0 = blockIdx.x * 128;
    const int col0 = blockIdx.y * 128;

    if (tid < 128) bias_s[tid] = bias[col0 + tid];

    float acc[4][4][4];
#pragma unroll
    for (int mi = 0; mi < 4; mi++)
#pragma unroll
        for (int ni = 0; ni < 4; ni++)
#pragma unroll
            for (int j = 0; j < 4; j++) acc[mi][ni][j] = 0.f;

    const int qr = lane >> 2;        // 0..7
    const int qc = lane & 3;         // 0..3

    for (int kc = 0; kc < 256; kc += KC) {
        // load A tile: 128 rows x 64 cols (8 float4 per thread)
#pragma unroll
        for (int i = 0; i < 8; i++) {
            int idx = tid + 256 * i;
            int r = idx >> 4, q = (idx & 15) * 4;
            int gr = row0 + r; if (gr >= nrows) gr = nrows - 1;
            float4 v = *(const float4*)(A + (size_t)gr * 256 + kc + q);
            float* d = As + r * LDT + q;
            d[0] = __uint_as_float(cvt_tf32(v.x));
            d[1] = __uint_as_float(cvt_tf32(v.y));
            d[2] = __uint_as_float(cvt_tf32(v.z));
            d[3] = __uint_as_float(cvt_tf32(v.w));
        }
        // load B tile: 128 n-rows x 64 k-cols
#pragma unroll
        for (int i = 0; i < 8; i++) {
            int idx = tid + 256 * i;
            int r = idx >> 4, q = (idx & 15) * 4;
            float4 v = *(const float4*)(Wt + (size_t)(col0 + r) * 256 + kc + q);
            float* d = Bs + r * LDT + q;
            d[0] = __uint_as_float(cvt_tf32(v.x));
            d[1] = __uint_as_float(cvt_tf32(v.y));
            d[2] = __uint_as_float(cvt_tf32(v.z));
            d[3] = __uint_as_float(cvt_tf32(v.w));
        }
        __syncthreads();

#pragma unroll
        for (int ks = 0; ks < KC; ks += 8) {
            uint32_t af[4][4], bf[4][2];
#pragma unroll
            for (int mi = 0; mi < 4; mi++) {
                const float* ab = As + (wm * 64 + mi * 16) * LDT + ks;
                af[mi][0] = __float_as_uint(ab[qr * LDT + qc]);
                af[mi][1] = __float_as_uint(ab[(qr + 8) * LDT + qc]);
                af[mi][2] = __float_as_uint(ab[qr * LDT + qc + 4]);
                af[mi][3] = __float_as_uint(ab[(qr + 8) * LDT + qc + 4]);
            }
#pragma unroll
            for (int ni = 0; ni < 4; ni++) {
                const float* bb = Bs + (wn * 32 + ni * 8 + qr) * LDT + ks;
                bf[ni][0] = __float_as_uint(bb[qc]);
                bf[ni][1] = __float_as_uint(bb[qc + 4]);
            }
#pragma unroll
            for (int mi = 0; mi < 4; mi++)
#pragma unroll
                for (int ni = 0; ni < 4; ni++) {
                    asm volatile(
                        "mma.sync.aligned.m16n8k8.row.col.f32.tf32.tf32.f32 "
                        "{%0,%1,%2,%3}, {%4,%5,%6,%7}, {%8,%9}, {%0,%1,%2,%3};"
                        : "+f"(acc[mi][ni][0]), "+f"(acc[mi][ni][1]),
                          "+f"(acc[mi][ni][2]), "+f"(acc[mi][ni][3])
                        : "r"(af[mi][0]), "r"(af[mi][1]), "r"(af[mi][2]), "r"(af[mi][3]),
                          "r"(bf[ni][0]), "r"(bf[ni][1]));
                }
        }
        __syncthreads();
    }

    // epilogue: bias + optional ELU, direct float2 stores (32B sectors)
#pragma unroll
    for (int mi = 0; mi < 4; mi++) {
        int r0 = row0 + wm * 64 + mi * 16 + qr;
#pragma unroll
        for (int ni = 0; ni < 4; ni++) {
            int cl = wn * 32 + ni * 8 + qc * 2;   // local col in [0,128)
            float b0 = bias_s[cl], b1 = bias_s[cl + 1];
            float v0 = acc[mi][ni][0] + b0, v1 = acc[mi][ni][1] + b1;
            float v2 = acc[mi][ni][2] + b0, v3 = acc[mi][ni][3] + b1;
            if (ELU) {
                v0 = (v0 > 0.f) ? v0 : expm1f(v0);
                v1 = (v1 > 0.f) ? v1 : expm1f(v1);
                v2 = (v2 > 0.f) ? v2 : expm1f(v2);
                v3 = (v3 > 0.f) ? v3 : expm1f(v3);
            }
            int cg = col0 + cl;
            if (r0 < nrows)
                *(float2*)(C + (size_t)r0 * 256 + cg) = make_float2(v0, v1);
            if (r0 + 8 < nrows)
                *(float2*)(C + (size_t)(r0 + 8) * 256 + cg) = make_float2(v2, v3);
        }
    }
}

// ---------------- LSTM gates GEMM ----------------
__global__ __launch_bounds__(256) void k_gates(
    const float* __restrict__ xin, int KW,
    const float* __restrict__ hold,
    const float* __restrict__ Wih, const float* __restrict__ Whh,
    float* __restrict__ gpart)
{
    __shared__ float a_s[32][33];
    __shared__ float w_s[32][33];
    const int tid = threadIdx.x;
    const int b0 = blockIdx.x * 32, j0 = blockIdx.y * 32;
    const int KT = KW + H_;
    const int khalf = KT >> 1;
    const int kbeg = blockIdx.z * khalf, kend = kbeg + khalf;
    const int ty = tid >> 4, tx = tid & 15;
    const int lr = tid >> 3, lc = (tid & 7) * 4;
    float a00 = 0.f, a01 = 0.f, a10 = 0.f, a11 = 0.f;

    for (int kt = kbeg; kt < kend; kt += 32) {
        const float *As, *Ws; int k, str;
        if (kt < KW) { As = xin;  Ws = Wih; k = kt;      str = KW; }
        else         { As = hold; Ws = Whh; k = kt - KW; str = H_; }
        float4 av = *(const float4*)(As + (size_t)(b0 + lr) * str + k + lc);
        a_s[lr][lc + 0] = av.x; a_s[lr][lc + 1] = av.y;
        a_s[lr][lc + 2] = av.z; a_s[lr][lc + 3] = av.w;
        float4 wv = *(const float4*)(Ws + (size_t)(j0 + lr) * str + k + lc);
        w_s[lr][lc + 0] = wv.x; w_s[lr][lc + 1] = wv.y;
        w_s[lr][lc + 2] = wv.z; w_s[lr][lc + 3] = wv.w;
        __syncthreads();
#pragma unroll
        for (int kk = 0; kk < 32; kk++) {
            float x0 = a_s[ty][kk], x1 = a_s[ty + 16][kk];
            float w0 = w_s[tx][kk], w1 = w_s[tx + 16][kk];
            a00 += x0 * w0; a01 += x0 * w1;
            a10 += x1 * w0; a11 += x1 * w1;
        }
        __syncthreads();
    }
    float* gp = gpart + (size_t)blockIdx.z * (B_ * 4 * H_);
    gp[(size_t)(b0 + ty)      * 1024 + j0 + tx]      = a00;
    gp[(size_t)(b0 + ty)      * 1024 + j0 + tx + 16] = a01;
    gp[(size_t)(b0 + ty + 16) * 1024 + j0 + tx]      = a10;
    gp[(size_t)(b0 + ty + 16) * 1024 + j0 + tx + 16] = a11;
}

// ---------------- LSTM cell elementwise ----------------
__device__ __forceinline__ float sigf(float x) { return 1.f / (1.f + expf(-x)); }

__global__ void k_update(const float* __restrict__ gp0, const float* __restrict__ gp1,
                         const float* __restrict__ bih, const float* __restrict__ bhh,
                         float* __restrict__ c, float* __restrict__ hnew,
                         float* __restrict__ qdst)
{
    int b = blockIdx.x, j = threadIdx.x;
    size_t g0 = (size_t)b * 1024;
    float iv = gp0[g0 + j]       + gp1[g0 + j]       + bih[j]       + bhh[j];
    float fv = gp0[g0 + 256 + j] + gp1[g0 + 256 + j] + bih[256 + j] + bhh[256 + j];
    float gv = gp0[g0 + 512 + j] + gp1[g0 + 512 + j] + bih[512 + j] + bhh[512 + j];
    float ov = gp0[g0 + 768 + j] + gp1[g0 + 768 + j] + bih[768 + j] + bhh[768 + j];
    float cn = sigf(fv) * c[b * H_ + j] + sigf(iv) * tanhf(gv);
    c[b * H_ + j] = cn;
    float hn = sigf(ov) * tanhf(cn);
    hnew[b * H_ + j] = hn;
    if (qdst) qdst[b * 2 * H_ + j] = hn;
}

// ---------------- segment attention ----------------
__global__ __launch_bounds__(256) void k_attn(
    const float* __restrict__ hfeat, const float* __restrict__ q,
    float* __restrict__ qstar)
{
    const int b = blockIdx.x, tid = threadIdx.x;
    const int s0 = g_seg[b], s1 = g_seg[b + 1];
    __shared__ float q_s[256];
    __shared__ float ws[256];
    __shared__ float red[10];
    q_s[tid] = q[b * 256 + tid];
    __syncthreads();

    const int lane = tid & 31, w = tid >> 5;
    float qreg[8];
#pragma unroll
    for (int k = 0; k < 8; k++) qreg[k] = q_s[lane + 32 * k];

    float mloc = -INFINITY;
    for (int n = s0 + w; n < s1; n += 8) {
        const float* hr = hfeat + (size_t)n * 256;
        float p = 0.f;
#pragma unroll
        for (int k = 0; k < 8; k++) p += hr[lane + 32 * k] * qreg[k];
#pragma unroll
        for (int off = 16; off; off >>= 1) p += __shfl_xor_sync(0xffffffffu, p, off);
        if (lane == 0) g_e[n] = p;
        mloc = fmaxf(mloc, p);
    }
    if (lane == 0) red[w] = mloc;
    __syncthreads();
    if (tid == 0) {
        float mm = -INFINITY;
        for (int i = 0; i < 8; i++) mm = fmaxf(mm, red[i]);
        red[8] = isfinite(mm) ? mm : 0.f;
    }
    __syncthreads();
    const float m = red[8];

    float acc0 = 0.f, acc1 = 0.f, acc2 = 0.f, acc3 = 0.f;
    float acc4 = 0.f, acc5 = 0.f, acc6 = 0.f, acc7 = 0.f, dpart = 0.f;
    for (int c0 = s0; c0 < s1; c0 += 256) {
        int cnt = min(256, s1 - c0);
        if (tid < cnt) {
            float wv = expf(g_e[c0 + tid] - m);
            ws[tid] = wv;
            dpart += wv;
        }
        __syncthreads();
        const float* base = hfeat + (size_t)c0 * 256 + tid;
        int i = 0;
        for (; i + 8 <= cnt; i += 8) {
            acc0 += ws[i]     * base[(size_t)i * 256];
            acc1 += ws[i + 1] * base[(size_t)(i + 1) * 256];
            acc2 += ws[i + 2] * base[(size_t)(i + 2) * 256];
            acc3 += ws[i + 3] * base[(size_t)(i + 3) * 256];
            acc4 += ws[i + 4] * base[(size_t)(i + 4) * 256];
            acc5 += ws[i + 5] * base[(size_t)(i + 5) * 256];
            acc6 += ws[i + 6] * base[(size_t)(i + 6) * 256];
            acc7 += ws[i + 7] * base[(size_t)(i + 7) * 256];
        }
        for (; i < cnt; i++) acc0 += ws[i] * base[(size_t)i * 256];
        __syncthreads();
    }
#pragma unroll
    for (int off = 16; off; off >>= 1) dpart += __shfl_xor_sync(0xffffffffu, dpart, off);
    if (lane == 0) red[w] = dpart;
    __syncthreads();
    if (tid == 0) {
        float s = 0.f;
        for (int i = 0; i < 8; i++) s += red[i];
        red[9] = s + 1e-16f;
    }
    __syncthreads();
    float denom = red[9];
    qstar[b * 2 * H_ + 256 + tid] =
        ((acc0 + acc1 + acc2 + acc3) + (acc4 + acc5 + acc6 + acc7)) / denom;
}

// ---------------- output projection ----------------
__global__ void k_out(const float* __restrict__ qstar, const float* __restrict__ W,
                      const float* __restrict__ bias, float* __restrict__ out)
{
    int b = blockIdx.x, e = threadIdx.x;
    __shared__ float qs[512];
    qs[e] = qstar[b * 512 + e];
    qs[e + 128] = qstar[b * 512 + e + 128];
    qs[e + 256] = qstar[b * 512 + e + 256];
    qs[e + 384] = qstar[b * 512 + e + 384];
    __syncthreads();
    float acc = bias[e];
#pragma unroll 8
    for (int k = 0; k < 512; k++) acc += qs[k] * W[k * E_ + e];
    out[b * E_ + e] = acc;
}

// ---------------- launch ----------------
extern "C" void kernel_launch(void* const* d_in, const int* in_sizes, int n_in,
                              void* d_out, int out_size)
{
    const float* x    = (const float*)d_in[0];
    const int*   bidx = (const int*)d_in[1];
    const float* W1   = (const float*)d_in[2];
    const float* b1   = (const float*)d_in[3];
    const float* W2   = (const float*)d_in[4];
    const float* b2   = (const float*)d_in[5];
    const float* Wih[3] = {(const float*)d_in[6],  (const float*)d_in[10], (const float*)d_in[14]};
    const float* Whh[3] = {(const float*)d_in[7],  (const float*)d_in[11], (const float*)d_in[15]};
    const float* bih[3] = {(const float*)d_in[8],  (const float*)d_in[12], (const float*)d_in[16]};
    const float* bhh[3] = {(const float*)d_in[9],  (const float*)d_in[13], (const float*)d_in[17]};
    const float* outW = (const float*)d_in[18];
    const float* outb = (const float*)d_in[19];
    float* out = (float*)d_out;

    const int N = in_sizes[0] / D_;

    float *tmp_p, *hfeat_p, *gpart_p, *hbuf_p, *c_p, *qstar_p, *wt1_p, *wt2_p;
    cudaGetSymbolAddress((void**)&tmp_p,   g_tmp);
    cudaGetSymbolAddress((void**)&hfeat_p, g_hfeat);
    cudaGetSymbolAddress((void**)&gpart_p, g_gpart);
    cudaGetSymbolAddress((void**)&hbuf_p,  g_hbuf);
    cudaGetSymbolAddress((void**)&c_p,     g_c);
    cudaGetSymbolAddress((void**)&qstar_p, g_qstar);
    cudaGetSymbolAddress((void**)&wt1_p,   g_Wt1);
    cudaGetSymbolAddress((void**)&wt2_p,   g_Wt2);

    cudaFuncSetAttribute(k_fnn_mma<true>,  cudaFuncAttributeMaxDynamicSharedMemorySize, SM_BYTES);
    cudaFuncSetAttribute(k_fnn_mma<false>, cudaFuncAttributeMaxDynamicSharedMemorySize, SM_BYTES);

    k_init<<<256, 256>>>();
    k_seg<<<1, B_ + 1>>>(bidx, N);
    dim3 tb(32, 32);
    dim3 tg(8, 8);
    k_transpose<<<tg, tb>>>(W1, wt1_p);
    k_transpose<<<tg, tb>>>(W2, wt2_p);

    dim3 fg((N + 127) / 128, 2);
    k_fnn_mma<true ><<<fg, 256, SM_BYTES>>>(x,     wt1_p, b1, tmp_p,   N);
    k_fnn_mma<false><<<fg, 256, SM_BYTES>>>(tmp_p, wt2_p, b2, hfeat_p, N);

    for (int s = 0; s < STEPS_; s++) {
        float* hold = hbuf_p + (size_t)(s & 1) * 3 * B_ * H_;
        float* hnew = hbuf_p + (size_t)((s & 1) ^ 1) * 3 * B_ * H_;
        for (int l = 0; l < 3; l++) {
            const float* xin = (l == 0) ? (const float*)qstar_p
                                        : (const float*)(hnew + (size_t)(l - 1) * B_ * H_);
            int KW = (l == 0) ? 2 * H_ : H_;
            dim3 gg(B_ / 32, 4 * H_ / 32, 2);
            k_gates<<<gg, 256>>>(xin, KW, hold + (size_t)l * B_ * H_,
                                 Wih[l], Whh[l], gpart_p);
            k_update<<<B_, H_>>>(gpart_p, gpart_p + (size_t)B_ * 4 * H_,
                                 bih[l], bhh[l],
                                 c_p + (size_t)l * B_ * H_,
                                 hnew + (size_t)l * B_ * H_,
                                 (l == 2) ? qstar_p : nullptr);
        }
        k_attn<<<B_, 256>>>(hfeat_p, hnew + (size_t)2 * B_ * H_, qstar_p);
    }
    k_out<<<B_, E_>>>(qstar_p, outW, outb, out);
}

// round 6
// speedup vs baseline: 1.7892x; 1.2830x over previous
#include <cuda_runtime.h>
#include <math.h>
#include <stdint.h>

#define D_ 256
#define H_ 256
#define B_ 128
#define E_ 128
#define STEPS_ 5
#define NMAX 100352

// ---------------- scratch (static __device__, no allocations) ----------------
__device__ __align__(16) float g_tmp[NMAX * H_];      // FNN layer1 out (ELU, tf32-rounded)
__device__ __align__(16) float g_hfeat[NMAX * H_];    // FNN output (fp32)
__device__ __align__(16) float g_gpart[2 * B_ * 4 * H_]; // split-K gate partials
__device__ float g_hbuf[2][3][B_ * H_];               // LSTM h ping-pong
__device__ float g_c[3][B_ * H_];                     // LSTM c
__device__ float g_qstar[B_ * 2 * H_];                // [q | r]
__device__ int   g_seg[B_ + 1];                       // segment offsets
__device__ __align__(16) float g_Wt1[D_ * H_];        // W1^T, tf32-rounded
__device__ __align__(16) float g_Wt2[H_ * H_];        // W2^T, tf32-rounded

__device__ __forceinline__ uint32_t cvt_tf32(float f) {
    uint32_t r;
    asm("cvt.rn.tf32.f32 %0, %1;" : "=r"(r) : "f"(f));
    return r;
}

// ---------------- init ----------------
__global__ void k_init() {
    int i = blockIdx.x * blockDim.x + threadIdx.x;
    int stride = gridDim.x * blockDim.x;
    for (int j = i; j < B_ * 2 * H_; j += stride) g_qstar[j] = 0.f;
    for (int j = i; j < 3 * B_ * H_; j += stride) {
        g_hbuf[0][0][j] = 0.f;
        g_hbuf[1][0][j] = 0.f;
        g_c[0][j] = 0.f;
    }
}

// ---------------- weight transpose + tf32 rounding (both weights, z-dim) -----
__global__ void k_transpose(const float* __restrict__ W1, const float* __restrict__ W2,
                            float* __restrict__ Wt1, float* __restrict__ Wt2) {
    __shared__ float t[32][33];
    const float* W  = blockIdx.z ? W2  : W1;
    float*       Wt = blockIdx.z ? Wt2 : Wt1;
    int bx = blockIdx.x * 32, by = blockIdx.y * 32;
    int tx = threadIdx.x, ty = threadIdx.y;
    t[ty][tx] = W[(by + ty) * 256 + bx + tx];
    __syncthreads();
    Wt[(bx + ty) * 256 + by + tx] = __uint_as_float(cvt_tf32(t[tx][ty]));
}

// ---------------- segment offsets ----------------
__global__ void k_seg(const int* __restrict__ idx, int N) {
    int b = threadIdx.x;
    if (b > B_) return;
    int lo = 0, hi = N;
    while (lo < hi) {
        int mid = (lo + hi) >> 1;
        if (idx[mid] < b) lo = mid + 1; else hi = mid;
    }
    g_seg[b] = lo;
}

// ---------------- FNN GEMM: tf32 HMMA + cp.async 2-stage pipeline ------------
// C[row0:+128, col0:+128] = act(A[.,256] @ Wt^T + bias)
// 256 thr = 8 warps (2M x 4N), warp tile 64x32 (4x4 m16n8k8), KC=64, 2 buffers.
#define KC 64
#define LDT 68
#define SM_TILE (128 * LDT)            // floats per tile
#define SM_BYTES (4 * SM_TILE * 4)     // 2 bufs x (A+B) = 139264 B

template <bool ELU, bool ROUND_OUT>
__global__ __launch_bounds__(256) void k_fnn_mma(
    const float* __restrict__ A, const float* __restrict__ Wt,
    const float* __restrict__ bias, float* __restrict__ C, int nrows)
{
    extern __shared__ float smem[];
    __shared__ float bias_s[128];

    const int tid  = threadIdx.x;
    const int lane = tid & 31;
    const int warp = tid >> 5;
    const int wm = warp >> 2;
    const int wn = warp & 3;
    const int row0 = blockIdx.x * 128;
    const int col0 = blockIdx.y * 128;

    if (tid < 128) bias_s[tid] = bias[col0 + tid];

    float acc[4][4][4];
#pragma unroll
    for (int mi = 0; mi < 4; mi++)
#pragma unroll
        for (int ni = 0; ni < 4; ni++)
#pragma unroll
            for (int j = 0; j < 4; j++) acc[mi][ni][j] = 0.f;

    const int qr = lane >> 2;
    const int qc = lane & 3;

    float* bufA[2] = { smem,               smem + 2 * SM_TILE };
    float* bufB[2] = { smem + SM_TILE,     smem + 3 * SM_TILE };

    const int ldr = tid >> 4;            // 0..15
    const int ldq = (tid & 15) * 4;      // 0..60

    // stage chunk kc into buffer s
    auto stage = [&](int kc, int s) {
#pragma unroll
        for (int i = 0; i < 8; i++) {
            int r = ldr + 16 * i;
            int gr = row0 + r; if (gr >= nrows) gr = nrows - 1;
            uint32_t d = (uint32_t)__cvta_generic_to_shared(bufA[s] + r * LDT + ldq);
            const float* sp = A + (size_t)gr * 256 + kc + ldq;
            asm volatile("cp.async.cg.shared.global [%0], [%1], 16;" :: "r"(d), "l"(sp) : "memory");
        }
#pragma unroll
        for (int i = 0; i < 8; i++) {
            int r = ldr + 16 * i;
            uint32_t d = (uint32_t)__cvta_generic_to_shared(bufB[s] + r * LDT + ldq);
            const float* sp = Wt + (size_t)(col0 + r) * 256 + kc + ldq;
            asm volatile("cp.async.cg.shared.global [%0], [%1], 16;" :: "r"(d), "l"(sp) : "memory");
        }
        asm volatile("cp.async.commit_group;" ::: "memory");
    };

    stage(0, 0);
    for (int c = 0; c < 4; c++) {
        if (c < 3) {
            stage((c + 1) * KC, (c + 1) & 1);
            asm volatile("cp.async.wait_group 1;" ::: "memory");
        } else {
            asm volatile("cp.async.wait_group 0;" ::: "memory");
        }
        __syncthreads();
        const float* As = bufA[c & 1];
        const float* Bs = bufB[c & 1];
#pragma unroll
        for (int ks = 0; ks < KC; ks += 8) {
            uint32_t af[4][4], bf[4][2];
#pragma unroll
            for (int mi = 0; mi < 4; mi++) {
                const float* ab = As + (wm * 64 + mi * 16) * LDT + ks;
                af[mi][0] = __float_as_uint(ab[qr * LDT + qc]);
                af[mi][1] = __float_as_uint(ab[(qr + 8) * LDT + qc]);
                af[mi][2] = __float_as_uint(ab[qr * LDT + qc + 4]);
                af[mi][3] = __float_as_uint(ab[(qr + 8) * LDT + qc + 4]);
            }
#pragma unroll
            for (int ni = 0; ni < 4; ni++) {
                const float* bb = Bs + (wn * 32 + ni * 8 + qr) * LDT + ks;
                bf[ni][0] = __float_as_uint(bb[qc]);
                bf[ni][1] = __float_as_uint(bb[qc + 4]);
            }
#pragma unroll
            for (int mi = 0; mi < 4; mi++)
#pragma unroll
                for (int ni = 0; ni < 4; ni++) {
                    asm volatile(
                        "mma.sync.aligned.m16n8k8.row.col.f32.tf32.tf32.f32 "
                        "{%0,%1,%2,%3}, {%4,%5,%6,%7}, {%8,%9}, {%0,%1,%2,%3};"
                        : "+f"(acc[mi][ni][0]), "+f"(acc[mi][ni][1]),
                          "+f"(acc[mi][ni][2]), "+f"(acc[mi][ni][3])
                        : "r"(af[mi][0]), "r"(af[mi][1]), "r"(af[mi][2]), "r"(af[mi][3]),
                          "r"(bf[ni][0]), "r"(bf[ni][1]));
                }
        }
        __syncthreads();
    }

    // epilogue: bias + optional ELU (+ optional tf32 rounding), float2 stores
#pragma unroll
    for (int mi = 0; mi < 4; mi++) {
        int r0 = row0 + wm * 64 + mi * 16 + qr;
#pragma unroll
        for (int ni = 0; ni < 4; ni++) {
            int cl = wn * 32 + ni * 8 + qc * 2;
            float b0 = bias_s[cl], b1 = bias_s[cl + 1];
            float v0 = acc[mi][ni][0] + b0, v1 = acc[mi][ni][1] + b1;
            float v2 = acc[mi][ni][2] + b0, v3 = acc[mi][ni][3] + b1;
            if (ELU) {
                v0 = (v0 > 0.f) ? v0 : expm1f(v0);
                v1 = (v1 > 0.f) ? v1 : expm1f(v1);
                v2 = (v2 > 0.f) ? v2 : expm1f(v2);
                v3 = (v3 > 0.f) ? v3 : expm1f(v3);
            }
            if (ROUND_OUT) {
                v0 = __uint_as_float(cvt_tf32(v0));
                v1 = __uint_as_float(cvt_tf32(v1));
                v2 = __uint_as_float(cvt_tf32(v2));
                v3 = __uint_as_float(cvt_tf32(v3));
            }
            int cg = col0 + cl;
            if (r0 < nrows)
                *(float2*)(C + (size_t)r0 * 256 + cg) = make_float2(v0, v1);
            if (r0 + 8 < nrows)
                *(float2*)(C + (size_t)(r0 + 8) * 256 + cg) = make_float2(v2, v3);
        }
    }
}

// ---------------- LSTM gates GEMM (fp32, split-K=2) ----------------
__global__ __launch_bounds__(256) void k_gates(
    const float* __restrict__ xin, int KW,
    const float* __restrict__ hold,
    const float* __restrict__ Wih, const float* __restrict__ Whh,
    float* __restrict__ gpart)
{
    __shared__ float a_s[32][33];
    __shared__ float w_s[32][33];
    const int tid = threadIdx.x;
    const int b0 = blockIdx.x * 32, j0 = blockIdx.y * 32;
    const int KT = KW + H_;
    const int khalf = KT >> 1;
    const int kbeg = blockIdx.z * khalf, kend = kbeg + khalf;
    const int ty = tid >> 4, tx = tid & 15;
    const int lr = tid >> 3, lc = (tid & 7) * 4;
    float a00 = 0.f, a01 = 0.f, a10 = 0.f, a11 = 0.f;

    for (int kt = kbeg; kt < kend; kt += 32) {
        const float *As, *Ws; int k, str;
        if (kt < KW) { As = xin;  Ws = Wih; k = kt;      str = KW; }
        else         { As = hold; Ws = Whh; k = kt - KW; str = H_; }
        float4 av = *(const float4*)(As + (size_t)(b0 + lr) * str + k + lc);
        a_s[lr][lc + 0] = av.x; a_s[lr][lc + 1] = av.y;
        a_s[lr][lc + 2] = av.z; a_s[lr][lc + 3] = av.w;
        float4 wv = *(const float4*)(Ws + (size_t)(j0 + lr) * str + k + lc);
        w_s[lr][lc + 0] = wv.x; w_s[lr][lc + 1] = wv.y;
        w_s[lr][lc + 2] = wv.z; w_s[lr][lc + 3] = wv.w;
        __syncthreads();
#pragma unroll
        for (int kk = 0; kk < 32; kk++) {
            float x0 = a_s[ty][kk], x1 = a_s[ty + 16][kk];
            float w0 = w_s[tx][kk], w1 = w_s[tx + 16][kk];
            a00 += x0 * w0; a01 += x0 * w1;
            a10 += x1 * w0; a11 += x1 * w1;
        }
        __syncthreads();
    }
    float* gp = gpart + (size_t)blockIdx.z * (B_ * 4 * H_);
    gp[(size_t)(b0 + ty)      * 1024 + j0 + tx]      = a00;
    gp[(size_t)(b0 + ty)      * 1024 + j0 + tx + 16] = a01;
    gp[(size_t)(b0 + ty + 16) * 1024 + j0 + tx]      = a10;
    gp[(size_t)(b0 + ty + 16) * 1024 + j0 + tx + 16] = a11;
}

// ---------------- LSTM cell elementwise ----------------
__device__ __forceinline__ float sigf(float x) { return 1.f / (1.f + expf(-x)); }

__global__ void k_update(const float* __restrict__ gp0, const float* __restrict__ gp1,
                         const float* __restrict__ bih, const float* __restrict__ bhh,
                         float* __restrict__ c, float* __restrict__ hnew,
                         float* __restrict__ qdst)
{
    int b = blockIdx.x, j = threadIdx.x;
    size_t g0 = (size_t)b * 1024;
    float iv = gp0[g0 + j]       + gp1[g0 + j]       + bih[j]       + bhh[j];
    float fv = gp0[g0 + 256 + j] + gp1[g0 + 256 + j] + bih[256 + j] + bhh[256 + j];
    float gv = gp0[g0 + 512 + j] + gp1[g0 + 512 + j] + bih[512 + j] + bhh[512 + j];
    float ov = gp0[g0 + 768 + j] + gp1[g0 + 768 + j] + bih[768 + j] + bhh[768 + j];
    float cn = sigf(fv) * c[b * H_ + j] + sigf(iv) * tanhf(gv);
    c[b * H_ + j] = cn;
    float hn = sigf(ov) * tanhf(cn);
    hnew[b * H_ + j] = hn;
    if (qdst) qdst[b * 2 * H_ + j] = hn;
}

// ---------------- segment attention: one-pass online softmax -----------------
// One block per segment, 512 threads (16 warps). Chunks of 64 nodes:
// 16 warps compute 4 dots each (rows land in L1), then 512 threads
// (= 256 cols x 2 node-halves) accumulate the weighted rows from L1.
__global__ __launch_bounds__(512) void k_attn(
    const float* __restrict__ hfeat, const float* __restrict__ q,
    float* __restrict__ qstar)
{
    const int b = blockIdx.x, tid = threadIdx.x;
    const int s0 = g_seg[b], s1 = g_seg[b + 1];
    __shared__ float q_s[256];
    __shared__ float e_s[64];
    __shared__ float racc[256];
    __shared__ float red[18];
    if (tid < 256) q_s[tid] = q[b * 256 + tid];
    __syncthreads();

    const int lane = tid & 31, warp = tid >> 5;
    const int col = tid & 255, half = tid >> 8;
    float qreg[8];
#pragma unroll
    for (int k = 0; k < 8; k++) qreg[k] = q_s[lane + 32 * k];

    float acc = 0.f, dpart = 0.f, m = -INFINITY;

    for (int c0 = s0; c0 < s1; c0 += 64) {
        const int cnt = min(64, s1 - c0);
        // dots: warp w handles local nodes w*4 .. w*4+3
#pragma unroll
        for (int i = 0; i < 4; i++) {
            int nl = warp * 4 + i;
            if (nl < cnt) {
                const float* hr = hfeat + (size_t)(c0 + nl) * 256;
                float p = 0.f;
#pragma unroll
                for (int k = 0; k < 8; k++) p += hr[lane + 32 * k] * qreg[k];
#pragma unroll
                for (int off = 16; off; off >>= 1) p += __shfl_xor_sync(0xffffffffu, p, off);
                if (lane == 0) e_s[nl] = p;
            }
        }
        __syncthreads();
        // chunk max (warp 0)
        if (warp == 0) {
            float v = (lane < cnt) ? e_s[lane] : -INFINITY;
            if (lane + 32 < cnt) v = fmaxf(v, e_s[lane + 32]);
#pragma unroll
            for (int off = 16; off; off >>= 1) v = fmaxf(v, __shfl_xor_sync(0xffffffffu, v, off));
            if (lane == 0) red[16] = v;
        }
        __syncthreads();
        const float mnew = fmaxf(m, red[16]);
        const float scale = expf(m - mnew);
        acc *= scale; dpart *= scale; m = mnew;
        if (tid < cnt) {
            float wv = expf(e_s[tid] - mnew);
            e_s[tid] = wv;
            dpart += wv;
        }
        __syncthreads();
        // weighted accumulation: half h covers local nodes [h*32, h*32+32)
        {
            const int i0 = half * 32;
            const int i1 = min(cnt, i0 + 32);
            const float* bp = hfeat + ((size_t)c0 + i0) * 256 + col;
            for (int i = i0; i < i1; i++, bp += 256) acc += e_s[i] * bp[0];
        }
        __syncthreads();
    }

    // reduce denom across block; combine the two node-halves per column
    float d = dpart;
#pragma unroll
    for (int off = 16; off; off >>= 1) d += __shfl_xor_sync(0xffffffffu, d, off);
    if (lane == 0) red[warp] = d;
    if (half == 0) racc[col] = acc;
    __syncthreads();
    if (tid == 0) {
        float s = 0.f;
        for (int i = 0; i < 16; i++) s += red[i];
        red[17] = s + 1e-16f;
    }
    __syncthreads();
    if (half == 1)
        qstar[b * 2 * H_ + 256 + col] = (racc[col] + acc) / red[17];
}

// ---------------- output projection ----------------
__global__ void k_out(const float* __restrict__ qstar, const float* __restrict__ W,
                      const float* __restrict__ bias, float* __restrict__ out)
{
    int b = blockIdx.x, e = threadIdx.x;
    __shared__ float qs[512];
    qs[e] = qstar[b * 512 + e];
    qs[e + 128] = qstar[b * 512 + e + 128];
    qs[e + 256] = qstar[b * 512 + e + 256];
    qs[e + 384] = qstar[b * 512 + e + 384];
    __syncthreads();
    float acc = bias[e];
#pragma unroll 8
    for (int k = 0; k < 512; k++) acc += qs[k] * W[k * E_ + e];
    out[b * E_ + e] = acc;
}

// ---------------- launch ----------------
extern "C" void kernel_launch(void* const* d_in, const int* in_sizes, int n_in,
                              void* d_out, int out_size)
{
    const float* x    = (const float*)d_in[0];
    const int*   bidx = (const int*)d_in[1];
    const float* W1   = (const float*)d_in[2];
    const float* b1   = (const float*)d_in[3];
    const float* W2   = (const float*)d_in[4];
    const float* b2   = (const float*)d_in[5];
    const float* Wih[3] = {(const float*)d_in[6],  (const float*)d_in[10], (const float*)d_in[14]};
    const float* Whh[3] = {(const float*)d_in[7],  (const float*)d_in[11], (const float*)d_in[15]};
    const float* bih[3] = {(const float*)d_in[8],  (const float*)d_in[12], (const float*)d_in[16]};
    const float* bhh[3] = {(const float*)d_in[9],  (const float*)d_in[13], (const float*)d_in[17]};
    const float* outW = (const float*)d_in[18];
    const float* outb = (const float*)d_in[19];
    float* out = (float*)d_out;

    const int N = in_sizes[0] / D_;

    float *tmp_p, *hfeat_p, *gpart_p, *hbuf_p, *c_p, *qstar_p, *wt1_p, *wt2_p;
    cudaGetSymbolAddress((void**)&tmp_p,   g_tmp);
    cudaGetSymbolAddress((void**)&hfeat_p, g_hfeat);
    cudaGetSymbolAddress((void**)&gpart_p, g_gpart);
    cudaGetSymbolAddress((void**)&hbuf_p,  g_hbuf);
    cudaGetSymbolAddress((void**)&c_p,     g_c);
    cudaGetSymbolAddress((void**)&qstar_p, g_qstar);
    cudaGetSymbolAddress((void**)&wt1_p,   g_Wt1);
    cudaGetSymbolAddress((void**)&wt2_p,   g_Wt2);

    cudaFuncSetAttribute(k_fnn_mma<true, true>,
                         cudaFuncAttributeMaxDynamicSharedMemorySize, SM_BYTES);
    cudaFuncSetAttribute(k_fnn_mma<false, false>,
                         cudaFuncAttributeMaxDynamicSharedMemorySize, SM_BYTES);

    k_init<<<256, 256>>>();
    k_seg<<<1, B_ + 1>>>(bidx, N);
    dim3 tb(32, 32);
    dim3 tg(8, 8, 2);
    k_transpose<<<tg, tb>>>(W1, W2, wt1_p, wt2_p);

    dim3 fg((N + 127) / 128, 2);
    k_fnn_mma<true, true ><<<fg, 256, SM_BYTES>>>(x,     wt1_p, b1, tmp_p,   N);
    k_fnn_mma<false, false><<<fg, 256, SM_BYTES>>>(tmp_p, wt2_p, b2, hfeat_p, N);

    for (int s = 0; s < STEPS_; s++) {
        float* hold = hbuf_p + (size_t)(s & 1) * 3 * B_ * H_;
        float* hnew = hbuf_p + (size_t)((s & 1) ^ 1) * 3 * B_ * H_;
        for (int l = 0; l < 3; l++) {
            const float* xin = (l == 0) ? (const float*)qstar_p
                                        : (const float*)(hnew + (size_t)(l - 1) * B_ * H_);
            int KW = (l == 0) ? 2 * H_ : H_;
            dim3 gg(B_ / 32, 4 * H_ / 32, 2);
            k_gates<<<gg, 256>>>(xin, KW, hold + (size_t)l * B_ * H_,
                                 Wih[l], Whh[l], gpart_p);
            k_update<<<B_, H_>>>(gpart_p, gpart_p + (size_t)B_ * 4 * H_,
                                 bih[l], bhh[l],
                                 c_p + (size_t)l * B_ * H_,
                                 hnew + (size_t)l * B_ * H_,
                                 (l == 2) ? qstar_p : nullptr);
        }
        k_attn<<<B_, 512>>>(hfeat_p, hnew + (size_t)2 * B_ * H_, qstar_p);
    }
    k_out<<<B_, E_>>>(qstar_p, outW, outb, out);
}